// round 1
// baseline (speedup 1.0000x reference)
#include <cuda_runtime.h>
#include <cuda_bf16.h>
#include <math.h>

// ---------------------------------------------------------------------------
// Problem constants
// ---------------------------------------------------------------------------
#define BATCH    32
#define SEQ_T    257                 // 1 CLS + 256 patches
#define ROWS_T   (BATCH * SEQ_T)     // 8224
#define EMBED_D  1024
#define NBLK     12
#define NHEAD    16
#define HDIM     64
#define QKV_D    3072
#define HID_D    2816
#define PATCH_M  (BATCH * 256)       // 8192
#define PATCH_K  768

// ---------------------------------------------------------------------------
// Scratch (static __device__ arrays; allocation is forbidden)
// ---------------------------------------------------------------------------
__device__ float g_a[(size_t)ROWS_T * EMBED_D];      // normed activations / patch tmp
__device__ float g_qkv[(size_t)ROWS_T * QKV_D];      // qkv projections
__device__ float g_o[(size_t)ROWS_T * EMBED_D];      // attention output
__device__ float g_gate[(size_t)ROWS_T * HID_D];     // silu(w1)*w3
__device__ float g_cond[(size_t)BATCH * EMBED_D];    // cond embedding
__device__ float g_fc[SEQ_T * 32 * 2];               // rope cos/sin

// ---------------------------------------------------------------------------
// Block reduction (256 threads)
// ---------------------------------------------------------------------------
__device__ __forceinline__ float block_reduce_sum(float v) {
    __shared__ float sh[8];
    int lane = threadIdx.x & 31;
    int w = threadIdx.x >> 5;
#pragma unroll
    for (int o = 16; o; o >>= 1) v += __shfl_xor_sync(0xffffffffu, v, o);
    if (lane == 0) sh[w] = v;
    __syncthreads();
    if (w == 0) {
        v = (lane < 8) ? sh[lane] : 0.f;
#pragma unroll
        for (int o = 4; o; o >>= 1) v += __shfl_xor_sync(0xffffffffu, v, o);
        if (lane == 0) sh[0] = v;
    }
    __syncthreads();
    float r = sh[0];
    __syncthreads();   // make repeated calls safe
    return r;
}

// ---------------------------------------------------------------------------
// RoPE table:  fc[s][j][0]=cos, [1]=sin ; row 0 (CLS) is zeros (matches ref!)
// ---------------------------------------------------------------------------
__global__ void freqs_kernel(float* __restrict__ fc) {
    int s = blockIdx.x;          // 0..256
    int j = threadIdx.x;         // 0..31
    float c = 0.f, sn = 0.f;
    if (s > 0) {
        int p = s - 1;
        int y = p >> 4, x = p & 15;
        int i = (j < 16) ? j : (j - 16);
        int t = (j < 16) ? y : x;
        float fr = powf(10000.0f, -(2.0f * (float)i) / 32.0f);
        float ang = (float)t * fr;
        c = cosf(ang);
        sn = sinf(ang);
    }
    fc[(s * 32 + j) * 2 + 0] = c;
    fc[(s * 32 + j) * 2 + 1] = sn;
}

// ---------------------------------------------------------------------------
// Tiled SGEMM: C[M,N] = A[M,K] @ B[K,N] (+bias) (+=C)
// BM=BN=64, BK=16, 256 threads, 4x4 per thread.
// Requires N % 64 == 0, K % 16 == 0 (true for all our shapes); M guarded.
// ---------------------------------------------------------------------------
template <bool BIAS, bool ACCUM>
__global__ void __launch_bounds__(256)
sgemm_kernel(const float* __restrict__ A, const float* __restrict__ B,
             const float* __restrict__ bias, float* __restrict__ C,
             int M, int N, int K) {
    __shared__ __align__(16) float As[64][17];
    __shared__ __align__(16) float Bs[16][64];

    const int tid = threadIdx.x;
    const int tx = tid & 15, ty = tid >> 4;
    const int rowBase = blockIdx.y * 64;
    const int colBase = blockIdx.x * 64;

    const int aRow = tid >> 2;            // 0..63
    const int aCol = (tid & 3) << 2;      // 0,4,8,12
    const int bRow = tid >> 4;            // 0..15
    const int bCol = (tid & 15) << 2;     // 0..60

    const bool aValid = (rowBase + aRow) < M;
    const float* Aptr = A + (size_t)(rowBase + aRow) * K + aCol;
    const float* Bptr = B + (size_t)bRow * N + colBase + bCol;

    float acc[4][4] = {};

    for (int k0 = 0; k0 < K; k0 += 16) {
        float4 av = aValid ? *(const float4*)(Aptr + k0) : make_float4(0, 0, 0, 0);
        float4 bv = *(const float4*)(Bptr + (size_t)k0 * N);
        As[aRow][aCol + 0] = av.x;
        As[aRow][aCol + 1] = av.y;
        As[aRow][aCol + 2] = av.z;
        As[aRow][aCol + 3] = av.w;
        *(float4*)&Bs[bRow][bCol] = bv;
        __syncthreads();
#pragma unroll
        for (int kk = 0; kk < 16; kk++) {
            float ra0 = As[ty * 4 + 0][kk];
            float ra1 = As[ty * 4 + 1][kk];
            float ra2 = As[ty * 4 + 2][kk];
            float ra3 = As[ty * 4 + 3][kk];
            float4 rb = *(const float4*)&Bs[kk][tx * 4];
            acc[0][0] += ra0 * rb.x; acc[0][1] += ra0 * rb.y; acc[0][2] += ra0 * rb.z; acc[0][3] += ra0 * rb.w;
            acc[1][0] += ra1 * rb.x; acc[1][1] += ra1 * rb.y; acc[1][2] += ra1 * rb.z; acc[1][3] += ra1 * rb.w;
            acc[2][0] += ra2 * rb.x; acc[2][1] += ra2 * rb.y; acc[2][2] += ra2 * rb.z; acc[2][3] += ra2 * rb.w;
            acc[3][0] += ra3 * rb.x; acc[3][1] += ra3 * rb.y; acc[3][2] += ra3 * rb.z; acc[3][3] += ra3 * rb.w;
        }
        __syncthreads();
    }

#pragma unroll
    for (int i = 0; i < 4; i++) {
        int row = rowBase + ty * 4 + i;
        if (row >= M) continue;
        float* Cp = C + (size_t)row * N + colBase + tx * 4;
#pragma unroll
        for (int j = 0; j < 4; j++) {
            float v = acc[i][j];
            if (BIAS) v += bias[colBase + tx * 4 + j];
            if (ACCUM) v += Cp[j];
            Cp[j] = v;
        }
    }
}

// ---------------------------------------------------------------------------
// Fused gated FFN GEMM: G = silu(A@W1) * (A@W3)
// ---------------------------------------------------------------------------
__global__ void __launch_bounds__(256)
gated_ffn_kernel(const float* __restrict__ A, const float* __restrict__ W1,
                 const float* __restrict__ W3, float* __restrict__ G,
                 int M, int N, int K) {
    __shared__ __align__(16) float As[64][17];
    __shared__ __align__(16) float B1s[16][64];
    __shared__ __align__(16) float B3s[16][64];

    const int tid = threadIdx.x;
    const int tx = tid & 15, ty = tid >> 4;
    const int rowBase = blockIdx.y * 64;
    const int colBase = blockIdx.x * 64;

    const int aRow = tid >> 2;
    const int aCol = (tid & 3) << 2;
    const int bRow = tid >> 4;
    const int bCol = (tid & 15) << 2;

    const bool aValid = (rowBase + aRow) < M;
    const float* Aptr = A + (size_t)(rowBase + aRow) * K + aCol;
    const float* B1p = W1 + (size_t)bRow * N + colBase + bCol;
    const float* B3p = W3 + (size_t)bRow * N + colBase + bCol;

    float acc1[4][4] = {};
    float acc3[4][4] = {};

    for (int k0 = 0; k0 < K; k0 += 16) {
        float4 av = aValid ? *(const float4*)(Aptr + k0) : make_float4(0, 0, 0, 0);
        float4 b1 = *(const float4*)(B1p + (size_t)k0 * N);
        float4 b3 = *(const float4*)(B3p + (size_t)k0 * N);
        As[aRow][aCol + 0] = av.x;
        As[aRow][aCol + 1] = av.y;
        As[aRow][aCol + 2] = av.z;
        As[aRow][aCol + 3] = av.w;
        *(float4*)&B1s[bRow][bCol] = b1;
        *(float4*)&B3s[bRow][bCol] = b3;
        __syncthreads();
#pragma unroll
        for (int kk = 0; kk < 16; kk++) {
            float ra[4];
#pragma unroll
            for (int i = 0; i < 4; i++) ra[i] = As[ty * 4 + i][kk];
            float4 r1 = *(const float4*)&B1s[kk][tx * 4];
            float4 r3 = *(const float4*)&B3s[kk][tx * 4];
#pragma unroll
            for (int i = 0; i < 4; i++) {
                acc1[i][0] += ra[i] * r1.x; acc1[i][1] += ra[i] * r1.y;
                acc1[i][2] += ra[i] * r1.z; acc1[i][3] += ra[i] * r1.w;
                acc3[i][0] += ra[i] * r3.x; acc3[i][1] += ra[i] * r3.y;
                acc3[i][2] += ra[i] * r3.z; acc3[i][3] += ra[i] * r3.w;
            }
        }
        __syncthreads();
    }

#pragma unroll
    for (int i = 0; i < 4; i++) {
        int row = rowBase + ty * 4 + i;
        if (row >= M) continue;
        float* Gp = G + (size_t)row * N + colBase + tx * 4;
#pragma unroll
        for (int j = 0; j < 4; j++) {
            float a1 = acc1[i][j];
            float sig = 1.0f / (1.0f + __expf(-a1));
            Gp[j] = a1 * sig * acc3[i][j];
        }
    }
}

// ---------------------------------------------------------------------------
// Embed combine (+pos) + LayerNorm -> h (d_out). One block per row.
// ---------------------------------------------------------------------------
__global__ void __launch_bounds__(256)
embed_ln_kernel(const float* __restrict__ patch, const float* __restrict__ cond,
                const float* __restrict__ pos, const float* __restrict__ g,
                const float* __restrict__ bta, float* __restrict__ h) {
    int row = blockIdx.x;
    int b = row / SEQ_T, s = row % SEQ_T;
    const float* src = (s == 0) ? (cond + (size_t)b * EMBED_D)
                                : (patch + ((size_t)b * 256 + (s - 1)) * EMBED_D);
    const float* pp = pos + (size_t)s * EMBED_D;

    float v[4];
    float sum = 0.f, sumsq = 0.f;
#pragma unroll
    for (int t = 0; t < 4; t++) {
        int idx = threadIdx.x + t * 256;
        float x = src[idx] + pp[idx];
        v[t] = x;
        sum += x;
        sumsq += x * x;
    }
    sum = block_reduce_sum(sum);
    sumsq = block_reduce_sum(sumsq);
    float mean = sum * (1.0f / EMBED_D);
    float var = sumsq * (1.0f / EMBED_D) - mean * mean;
    float inv = rsqrtf(var + 1e-6f);
#pragma unroll
    for (int t = 0; t < 4; t++) {
        int idx = threadIdx.x + t * 256;
        h[(size_t)row * EMBED_D + idx] = (v[t] - mean) * inv * g[idx] + bta[idx];
    }
}

// ---------------------------------------------------------------------------
// RMSNorm: out = x * rsqrt(mean(x^2)+eps) * w. One block per row.
// ---------------------------------------------------------------------------
__global__ void __launch_bounds__(256)
rmsnorm_kernel(const float* __restrict__ x, const float* __restrict__ w,
               float* __restrict__ out) {
    int row = blockIdx.x;
    const float* xp = x + (size_t)row * EMBED_D;
    float v[4];
    float ss = 0.f;
#pragma unroll
    for (int t = 0; t < 4; t++) {
        int idx = threadIdx.x + t * 256;
        v[t] = xp[idx];
        ss += v[t] * v[t];
    }
    ss = block_reduce_sum(ss);
    float inv = rsqrtf(ss * (1.0f / EMBED_D) + 1e-5f);
#pragma unroll
    for (int t = 0; t < 4; t++) {
        int idx = threadIdx.x + t * 256;
        out[(size_t)row * EMBED_D + idx] = v[t] * inv * w[idx];
    }
}

// ---------------------------------------------------------------------------
// Flash attention (fp32), RoPE fused into Q/K tile loads.
// grid (qtile=5, head=16, batch=32), 256 threads, 64x64 tiles.
// dynamic smem: Qs,Ks,Vs,Ps each 64x65 floats = 66560 B
// ---------------------------------------------------------------------------
#define ATTN_SMEM (4 * 64 * 65 * 4)

__global__ void __launch_bounds__(256)
attn_kernel(const float* __restrict__ qkv, const float* __restrict__ fc,
            float* __restrict__ o) {
    extern __shared__ float sm[];
    float* Qs = sm;                 // [64][65]
    float* Ks = sm + 64 * 65;
    float* Vs = sm + 2 * 64 * 65;
    float* Ps = sm + 3 * 64 * 65;

    const int qt = blockIdx.x;
    const int hh = blockIdx.y;
    const int bb = blockIdx.z;
    const int tid = threadIdx.x;
    const int tx = tid & 15, ty = tid >> 4;
    const int lr = tid >> 4;         // 0..15
    const int ld = (tid & 15) << 2;  // 0..60

    const size_t bhBase = (size_t)bb * SEQ_T * QKV_D + (size_t)hh * HDIM;

    // ---- load Q tile with RoPE ----
#pragma unroll
    for (int i = 0; i < 4; i++) {
        int r = lr + 16 * i;
        int gq = qt * 64 + r;
        float q0 = 0, q1 = 0, q2 = 0, q3 = 0;
        if (gq < SEQ_T) {
            float4 v = *(const float4*)(qkv + bhBase + (size_t)gq * QKV_D + ld);
            int j0 = ld >> 1;
            float c0 = fc[(gq * 32 + j0) * 2 + 0], s0 = fc[(gq * 32 + j0) * 2 + 1];
            float c1 = fc[(gq * 32 + j0 + 1) * 2 + 0], s1 = fc[(gq * 32 + j0 + 1) * 2 + 1];
            q0 = v.x * c0 - v.y * s0;
            q1 = v.y * c0 + v.x * s0;
            q2 = v.z * c1 - v.w * s1;
            q3 = v.w * c1 + v.z * s1;
        }
        Qs[r * 65 + ld + 0] = q0;
        Qs[r * 65 + ld + 1] = q1;
        Qs[r * 65 + ld + 2] = q2;
        Qs[r * 65 + ld + 3] = q3;
    }

    float oacc[4][4] = {};
    float m[4], l[4];
#pragma unroll
    for (int i = 0; i < 4; i++) { m[i] = -1e30f; l[i] = 0.f; }

    const int nkt = qt + 1;   // causal: only tiles <= qt
    for (int kt = 0; kt < nkt; kt++) {
        // ---- load K (with RoPE) and V tiles ----
#pragma unroll
        for (int i = 0; i < 4; i++) {
            int r = lr + 16 * i;
            int gk = kt * 64 + r;
            float k0 = 0, k1 = 0, k2 = 0, k3 = 0, v0 = 0, v1 = 0, v2 = 0, v3 = 0;
            if (gk < SEQ_T) {
                float4 kv = *(const float4*)(qkv + bhBase + (size_t)gk * QKV_D + 1024 + ld);
                float4 vv = *(const float4*)(qkv + bhBase + (size_t)gk * QKV_D + 2048 + ld);
                int j0 = ld >> 1;
                float c0 = fc[(gk * 32 + j0) * 2 + 0], s0 = fc[(gk * 32 + j0) * 2 + 1];
                float c1 = fc[(gk * 32 + j0 + 1) * 2 + 0], s1 = fc[(gk * 32 + j0 + 1) * 2 + 1];
                k0 = kv.x * c0 - kv.y * s0;
                k1 = kv.y * c0 + kv.x * s0;
                k2 = kv.z * c1 - kv.w * s1;
                k3 = kv.w * c1 + kv.z * s1;
                v0 = vv.x; v1 = vv.y; v2 = vv.z; v3 = vv.w;
            }
            Ks[r * 65 + ld + 0] = k0;
            Ks[r * 65 + ld + 1] = k1;
            Ks[r * 65 + ld + 2] = k2;
            Ks[r * 65 + ld + 3] = k3;
            Vs[r * 65 + ld + 0] = v0;
            Vs[r * 65 + ld + 1] = v1;
            Vs[r * 65 + ld + 2] = v2;
            Vs[r * 65 + ld + 3] = v3;
        }
        __syncthreads();

        // ---- S = Q K^T ----
        float s[4][4] = {};
#pragma unroll 4
        for (int d = 0; d < 64; d++) {
            float ra[4], rb[4];
#pragma unroll
            for (int i = 0; i < 4; i++) ra[i] = Qs[(ty * 4 + i) * 65 + d];
#pragma unroll
            for (int j = 0; j < 4; j++) rb[j] = Ks[(tx * 4 + j) * 65 + d];
#pragma unroll
            for (int i = 0; i < 4; i++)
#pragma unroll
                for (int j = 0; j < 4; j++) s[i][j] += ra[i] * rb[j];
        }

        // ---- mask, online softmax ----
#pragma unroll
        for (int i = 0; i < 4; i++) {
            int gq = qt * 64 + ty * 4 + i;
            float rm = -1e30f;
#pragma unroll
            for (int j = 0; j < 4; j++) {
                int gk = kt * 64 + tx * 4 + j;
                float sv = s[i][j] * 0.125f;
                if (gk > gq || gk >= SEQ_T) sv = -1e30f;
                s[i][j] = sv;
                rm = fmaxf(rm, sv);
            }
#pragma unroll
            for (int off = 8; off; off >>= 1)
                rm = fmaxf(rm, __shfl_xor_sync(0xffffffffu, rm, off));
            float newm = fmaxf(m[i], rm);
            float corr = __expf(m[i] - newm);
            float rs = 0.f;
#pragma unroll
            for (int j = 0; j < 4; j++) {
                float p = __expf(s[i][j] - newm);
                s[i][j] = p;
                rs += p;
            }
#pragma unroll
            for (int off = 8; off; off >>= 1)
                rs += __shfl_xor_sync(0xffffffffu, rs, off);
            l[i] = l[i] * corr + rs;
            m[i] = newm;
#pragma unroll
            for (int j = 0; j < 4; j++) oacc[i][j] *= corr;
        }

        // ---- write P, then O += P @ V ----
#pragma unroll
        for (int i = 0; i < 4; i++)
#pragma unroll
            for (int j = 0; j < 4; j++)
                Ps[(ty * 4 + i) * 65 + tx * 4 + j] = s[i][j];
        __syncthreads();

#pragma unroll 4
        for (int d = 0; d < 64; d++) {
            float ra[4], rb[4];
#pragma unroll
            for (int i = 0; i < 4; i++) ra[i] = Ps[(ty * 4 + i) * 65 + d];
#pragma unroll
            for (int j = 0; j < 4; j++) rb[j] = Vs[d * 65 + tx * 4 + j];
#pragma unroll
            for (int i = 0; i < 4; i++)
#pragma unroll
                for (int j = 0; j < 4; j++) oacc[i][j] += ra[i] * rb[j];
        }
        __syncthreads();
    }

    // ---- store O (layout b,q,h,d) ----
#pragma unroll
    for (int i = 0; i < 4; i++) {
        int gq = qt * 64 + ty * 4 + i;
        if (gq >= SEQ_T) continue;
        float inv = 1.0f / l[i];
        float* op = o + ((size_t)bb * SEQ_T + gq) * EMBED_D + hh * HDIM + tx * 4;
        float4 r;
        r.x = oacc[i][0] * inv;
        r.y = oacc[i][1] * inv;
        r.z = oacc[i][2] * inv;
        r.w = oacc[i][3] * inv;
        *(float4*)op = r;
    }
}

// ---------------------------------------------------------------------------
// Launcher
// ---------------------------------------------------------------------------
extern "C" void kernel_launch(void* const* d_in, const int* in_sizes, int n_in,
                              void* d_out, int out_size) {
    const float* x       = (const float*)d_in[0];   // [32,256,768]
    const float* cond    = (const float*)d_in[1];   // [32,1024]
    const float* patch_w = (const float*)d_in[2];   // [768,1024]
    const float* patch_b = (const float*)d_in[3];   // [1024]
    const float* ln_g    = (const float*)d_in[4];   // [1024]
    const float* ln_b    = (const float*)d_in[5];   // [1024]
    const float* pos     = (const float*)d_in[6];   // [1,257,1024]
    const float* cond_w  = (const float*)d_in[7];   // [1024,1024]
    const float* cond_b  = (const float*)d_in[8];   // [1024]
    const float* wqkv    = (const float*)d_in[9];   // [12,1024,3072]
    const float* wo      = (const float*)d_in[10];  // [12,1024,1024]
    const float* w1      = (const float*)d_in[11];  // [12,1024,2816]
    const float* w2      = (const float*)d_in[12];  // [12,2816,1024]
    const float* w3      = (const float*)d_in[13];  // [12,1024,2816]
    const float* anw     = (const float*)d_in[14];  // [12,1024]
    const float* fnw     = (const float*)d_in[15];  // [12,1024]

    float* h = (float*)d_out;                       // residual stream lives in d_out

    float *a, *qkvb, *ob, *gate, *condb, *fc;
    cudaGetSymbolAddress((void**)&a, g_a);
    cudaGetSymbolAddress((void**)&qkvb, g_qkv);
    cudaGetSymbolAddress((void**)&ob, g_o);
    cudaGetSymbolAddress((void**)&gate, g_gate);
    cudaGetSymbolAddress((void**)&condb, g_cond);
    cudaGetSymbolAddress((void**)&fc, g_fc);

    cudaFuncSetAttribute(attn_kernel, cudaFuncAttributeMaxDynamicSharedMemorySize,
                         ATTN_SMEM);

    // RoPE table
    freqs_kernel<<<SEQ_T, 32>>>(fc);

    // patch embed -> g_a (as [8192,1024]); cond embed -> g_cond
    sgemm_kernel<true, false><<<dim3(EMBED_D / 64, PATCH_M / 64), 256>>>(
        x, patch_w, patch_b, a, PATCH_M, EMBED_D, PATCH_K);
    sgemm_kernel<true, false><<<dim3(EMBED_D / 64, 1), 256>>>(
        cond, cond_w, cond_b, condb, BATCH, EMBED_D, EMBED_D);

    // concat + pos + layernorm -> h
    embed_ln_kernel<<<ROWS_T, 256>>>(a, condb, pos, ln_g, ln_b, h);

    const int gy = (ROWS_T + 63) / 64;  // 129

    for (int blk = 0; blk < NBLK; blk++) {
        const float* Wqkv = wqkv + (size_t)blk * EMBED_D * QKV_D;
        const float* Wo   = wo   + (size_t)blk * EMBED_D * EMBED_D;
        const float* W1   = w1   + (size_t)blk * EMBED_D * HID_D;
        const float* W2   = w2   + (size_t)blk * HID_D * EMBED_D;
        const float* W3   = w3   + (size_t)blk * EMBED_D * HID_D;

        // attn pre-norm
        rmsnorm_kernel<<<ROWS_T, 256>>>(h, anw + blk * EMBED_D, a);
        // qkv projection
        sgemm_kernel<false, false><<<dim3(QKV_D / 64, gy), 256>>>(
            a, Wqkv, nullptr, qkvb, ROWS_T, QKV_D, EMBED_D);
        // attention (rope fused)
        attn_kernel<<<dim3(5, NHEAD, BATCH), 256, ATTN_SMEM>>>(qkvb, fc, ob);
        // output projection + residual
        sgemm_kernel<false, true><<<dim3(EMBED_D / 64, gy), 256>>>(
            ob, Wo, nullptr, h, ROWS_T, EMBED_D, EMBED_D);
        // ffn pre-norm
        rmsnorm_kernel<<<ROWS_T, 256>>>(h, fnw + blk * EMBED_D, a);
        // gated ffn up: silu(a@W1)*(a@W3)
        gated_ffn_kernel<<<dim3(HID_D / 64, gy), 256>>>(
            a, W1, W3, gate, ROWS_T, HID_D, EMBED_D);
        // ffn down + residual
        sgemm_kernel<false, true><<<dim3(EMBED_D / 64, gy), 256>>>(
            gate, W2, nullptr, h, ROWS_T, EMBED_D, HID_D);
    }
}

// round 4
// speedup vs baseline: 1.9974x; 1.9974x over previous
#include <cuda_runtime.h>
#include <cuda_bf16.h>
#include <math.h>

// ---------------------------------------------------------------------------
// Problem constants
// ---------------------------------------------------------------------------
#define BATCH    32
#define SEQ_T    257                 // 1 CLS + 256 patches
#define ROWS_T   (BATCH * SEQ_T)     // 8224
#define EMBED_D  1024
#define NBLK     12
#define NHEAD    16
#define HDIM     64
#define QKV_D    3072
#define HID_D    2816
#define PATCH_M  (BATCH * 256)       // 8192
#define PATCH_K  768

// ---------------------------------------------------------------------------
// Scratch (static __device__ arrays; allocation is forbidden)
// ---------------------------------------------------------------------------
__device__ float g_a[(size_t)ROWS_T * EMBED_D];      // normed activations / patch tmp
__device__ float g_qkv[(size_t)ROWS_T * QKV_D];      // qkv projections
__device__ float g_o[(size_t)ROWS_T * EMBED_D];      // attention output
__device__ float g_gate[(size_t)ROWS_T * HID_D];     // w1 out, then silu(w1)*w3
__device__ float g_cond[(size_t)BATCH * EMBED_D];    // cond embedding
__device__ float g_fc[SEQ_T * 32 * 2];               // rope cos/sin

// ---------------------------------------------------------------------------
// Block reduction (256 threads)
// ---------------------------------------------------------------------------
__device__ __forceinline__ float block_reduce_sum(float v) {
    __shared__ float sh[8];
    int lane = threadIdx.x & 31;
    int w = threadIdx.x >> 5;
#pragma unroll
    for (int o = 16; o; o >>= 1) v += __shfl_xor_sync(0xffffffffu, v, o);
    if (lane == 0) sh[w] = v;
    __syncthreads();
    if (w == 0) {
        v = (lane < 8) ? sh[lane] : 0.f;
#pragma unroll
        for (int o = 4; o; o >>= 1) v += __shfl_xor_sync(0xffffffffu, v, o);
        if (lane == 0) sh[0] = v;
    }
    __syncthreads();
    float r = sh[0];
    __syncthreads();
    return r;
}

// ---------------------------------------------------------------------------
// RoPE table:  fc[s][j][0]=cos, [1]=sin ; row 0 (CLS) is zeros (matches ref)
// ---------------------------------------------------------------------------
__global__ void freqs_kernel(float* __restrict__ fc) {
    int s = blockIdx.x;          // 0..256
    int j = threadIdx.x;         // 0..31
    float c = 0.f, sn = 0.f;
    if (s > 0) {
        int p = s - 1;
        int y = p >> 4, x = p & 15;
        int i = (j < 16) ? j : (j - 16);
        int t = (j < 16) ? y : x;
        float fr = powf(10000.0f, -(2.0f * (float)i) / 32.0f);
        float ang = (float)t * fr;
        c = cosf(ang);
        sn = sinf(ang);
    }
    fc[(s * 32 + j) * 2 + 0] = c;
    fc[(s * 32 + j) * 2 + 1] = sn;
}

// ---------------------------------------------------------------------------
// TF32 helpers
// ---------------------------------------------------------------------------
__device__ __forceinline__ float f2tf32(float f) {
    unsigned u;
    asm("cvt.rna.tf32.f32 %0, %1;" : "=r"(u) : "f"(f));
    return __uint_as_float(u);
}

__device__ __forceinline__ void mma_tf32(float* c, const unsigned* a,
                                         const unsigned* b) {
    asm volatile(
        "mma.sync.aligned.m16n8k8.row.col.f32.tf32.tf32.f32 "
        "{%0,%1,%2,%3}, {%4,%5,%6,%7}, {%8,%9}, {%0,%1,%2,%3};\n"
        : "+f"(c[0]), "+f"(c[1]), "+f"(c[2]), "+f"(c[3])
        : "r"(a[0]), "r"(a[1]), "r"(a[2]), "r"(a[3]), "r"(b[0]), "r"(b[1]));
}

// ---------------------------------------------------------------------------
// TF32 tensor-core GEMM: C[M,N] = A[M,K] @ B[K,N]  (epilogue per MODE)
// MODE 0: store   1: +bias   2: += C (residual)   3: silu(C)*acc (gate)
// BM=BN=128, BK=16, 256 threads (8 warps, 2x4 of 64x32 warp tiles).
// Requires N % 128 == 0, K % 16 == 0; M guarded.
// ---------------------------------------------------------------------------
#define A_STRIDE 20    // conflict-free for A-fragment reads
#define B_STRIDE 136   // conflict-free for B-fragment reads

template <int MODE>
__global__ void __launch_bounds__(256)
mma_gemm(const float* __restrict__ A, const float* __restrict__ B,
         const float* __restrict__ bias, float* __restrict__ C,
         int M, int N, int K) {
    __shared__ float As[128 * A_STRIDE];   // [m][k]
    __shared__ float Bs[16 * B_STRIDE];    // [k][n]

    const int tid = threadIdx.x;
    const int lane = tid & 31;
    const int warp = tid >> 5;
    const int gid = lane >> 2;     // 0..7
    const int ctg = lane & 3;      // 0..3
    const int mw = (warp & 1) * 64;
    const int nw = (warp >> 1) * 32;

    const int rowBase = blockIdx.y * 128;
    const int colBase = blockIdx.x * 128;

    // global load mapping
    const int aRow = tid >> 1;           // 0..127
    const int aK = (tid & 1) * 8;        // 0 or 8
    const int bK = tid >> 4;             // 0..15
    const int bCol = (tid & 15) * 8;     // 0..120

    const bool aValid = (rowBase + aRow) < M;
    const float* Ap = A + (size_t)(rowBase + aRow) * K + aK;
    const float* Bp = B + (size_t)bK * N + colBase + bCol;

    float acc[4][4][4] = {};   // [mi][ni][frag]

    float4 pa0, pa1, pb0, pb1;
    // prefetch iter 0
    pa0 = aValid ? *(const float4*)(Ap + 0) : make_float4(0, 0, 0, 0);
    pa1 = aValid ? *(const float4*)(Ap + 4) : make_float4(0, 0, 0, 0);
    pb0 = *(const float4*)(Bp + 0);
    pb1 = *(const float4*)(Bp + 4);

    for (int k0 = 0; k0 < K; k0 += 16) {
        // commit prefetched tile to smem (tf32-rounded)
        float* as = &As[aRow * A_STRIDE + aK];
        as[0] = f2tf32(pa0.x); as[1] = f2tf32(pa0.y);
        as[2] = f2tf32(pa0.z); as[3] = f2tf32(pa0.w);
        as[4] = f2tf32(pa1.x); as[5] = f2tf32(pa1.y);
        as[6] = f2tf32(pa1.z); as[7] = f2tf32(pa1.w);
        float* bs = &Bs[bK * B_STRIDE + bCol];
        bs[0] = f2tf32(pb0.x); bs[1] = f2tf32(pb0.y);
        bs[2] = f2tf32(pb0.z); bs[3] = f2tf32(pb0.w);
        bs[4] = f2tf32(pb1.x); bs[5] = f2tf32(pb1.y);
        bs[6] = f2tf32(pb1.z); bs[7] = f2tf32(pb1.w);
        __syncthreads();

        // prefetch next tile
        if (k0 + 16 < K) {
            pa0 = aValid ? *(const float4*)(Ap + k0 + 16) : make_float4(0, 0, 0, 0);
            pa1 = aValid ? *(const float4*)(Ap + k0 + 20) : make_float4(0, 0, 0, 0);
            pb0 = *(const float4*)(Bp + (size_t)(k0 + 16) * N);
            pb1 = *(const float4*)(Bp + (size_t)(k0 + 16) * N + 4);
        }

        // compute: 2 k-steps of 8
#pragma unroll
        for (int ks = 0; ks < 16; ks += 8) {
            unsigned af[4][4], bf[4][2];
#pragma unroll
            for (int mi = 0; mi < 4; mi++) {
                const int r0 = (mw + mi * 16 + gid) * A_STRIDE;
                const int r8 = r0 + 8 * A_STRIDE;
                af[mi][0] = __float_as_uint(As[r0 + ks + ctg]);
                af[mi][1] = __float_as_uint(As[r8 + ks + ctg]);
                af[mi][2] = __float_as_uint(As[r0 + ks + ctg + 4]);
                af[mi][3] = __float_as_uint(As[r8 + ks + ctg + 4]);
            }
#pragma unroll
            for (int ni = 0; ni < 4; ni++) {
                bf[ni][0] = __float_as_uint(Bs[(ks + ctg) * B_STRIDE + nw + ni * 8 + gid]);
                bf[ni][1] = __float_as_uint(Bs[(ks + ctg + 4) * B_STRIDE + nw + ni * 8 + gid]);
            }
#pragma unroll
            for (int mi = 0; mi < 4; mi++)
#pragma unroll
                for (int ni = 0; ni < 4; ni++)
                    mma_tf32(acc[mi][ni], af[mi], bf[ni]);
        }
        __syncthreads();
    }

    // epilogue
#pragma unroll
    for (int mi = 0; mi < 4; mi++) {
#pragma unroll
        for (int half = 0; half < 2; half++) {
            int row = rowBase + mw + mi * 16 + gid + half * 8;
            if (row >= M) continue;
#pragma unroll
            for (int ni = 0; ni < 4; ni++) {
                int col = colBase + nw + ni * 8 + 2 * ctg;
                float v0 = acc[mi][ni][half * 2 + 0];
                float v1 = acc[mi][ni][half * 2 + 1];
                float* Cp = C + (size_t)row * N + col;
                if (MODE == 1) {
                    v0 += bias[col];
                    v1 += bias[col + 1];
                } else if (MODE == 2) {
                    float2 old = *(const float2*)Cp;
                    v0 += old.x;
                    v1 += old.y;
                } else if (MODE == 3) {
                    float2 g = *(const float2*)Cp;
                    v0 *= g.x / (1.0f + __expf(-g.x));
                    v1 *= g.y / (1.0f + __expf(-g.y));
                }
                float2 out;
                out.x = v0;
                out.y = v1;
                *(float2*)Cp = out;
            }
        }
    }
}

// ---------------------------------------------------------------------------
// Embed combine (+pos) + LayerNorm -> h (d_out). One block per row.
// ---------------------------------------------------------------------------
__global__ void __launch_bounds__(256)
embed_ln_kernel(const float* __restrict__ patch, const float* __restrict__ cond,
                const float* __restrict__ pos, const float* __restrict__ g,
                const float* __restrict__ bta, float* __restrict__ h) {
    int row = blockIdx.x;
    int b = row / SEQ_T, s = row % SEQ_T;
    const float* src = (s == 0) ? (cond + (size_t)b * EMBED_D)
                                : (patch + ((size_t)b * 256 + (s - 1)) * EMBED_D);
    const float* pp = pos + (size_t)s * EMBED_D;

    float v[4];
    float sum = 0.f, sumsq = 0.f;
#pragma unroll
    for (int t = 0; t < 4; t++) {
        int idx = threadIdx.x + t * 256;
        float x = src[idx] + pp[idx];
        v[t] = x;
        sum += x;
        sumsq += x * x;
    }
    sum = block_reduce_sum(sum);
    sumsq = block_reduce_sum(sumsq);
    float mean = sum * (1.0f / EMBED_D);
    float var = sumsq * (1.0f / EMBED_D) - mean * mean;
    float inv = rsqrtf(var + 1e-6f);
#pragma unroll
    for (int t = 0; t < 4; t++) {
        int idx = threadIdx.x + t * 256;
        h[(size_t)row * EMBED_D + idx] = (v[t] - mean) * inv * g[idx] + bta[idx];
    }
}

// ---------------------------------------------------------------------------
// RMSNorm: out = x * rsqrt(mean(x^2)+eps) * w. One block per row.
// ---------------------------------------------------------------------------
__global__ void __launch_bounds__(256)
rmsnorm_kernel(const float* __restrict__ x, const float* __restrict__ w,
               float* __restrict__ out) {
    int row = blockIdx.x;
    const float* xp = x + (size_t)row * EMBED_D;
    float v[4];
    float ss = 0.f;
#pragma unroll
    for (int t = 0; t < 4; t++) {
        int idx = threadIdx.x + t * 256;
        v[t] = xp[idx];
        ss += v[t] * v[t];
    }
    ss = block_reduce_sum(ss);
    float inv = rsqrtf(ss * (1.0f / EMBED_D) + 1e-5f);
#pragma unroll
    for (int t = 0; t < 4; t++) {
        int idx = threadIdx.x + t * 256;
        out[(size_t)row * EMBED_D + idx] = v[t] * inv * w[idx];
    }
}

// ---------------------------------------------------------------------------
// Flash attention (fp32), RoPE fused into Q/K tile loads.
// grid (qtile=5, head=16, batch=32), 256 threads, 64x64 tiles.
// ---------------------------------------------------------------------------
#define ATTN_SMEM (4 * 64 * 65 * 4)

__global__ void __launch_bounds__(256)
attn_kernel(const float* __restrict__ qkv, const float* __restrict__ fc,
            float* __restrict__ o) {
    extern __shared__ float sm[];
    float* Qs = sm;                 // [64][65]
    float* Ks = sm + 64 * 65;
    float* Vs = sm + 2 * 64 * 65;
    float* Ps = sm + 3 * 64 * 65;

    const int qt = blockIdx.x;
    const int hh = blockIdx.y;
    const int bb = blockIdx.z;
    const int tid = threadIdx.x;
    const int tx = tid & 15, ty = tid >> 4;
    const int lr = tid >> 4;         // 0..15
    const int ld = (tid & 15) << 2;  // 0..60

    const size_t bhBase = (size_t)bb * SEQ_T * QKV_D + (size_t)hh * HDIM;

#pragma unroll
    for (int i = 0; i < 4; i++) {
        int r = lr + 16 * i;
        int gq = qt * 64 + r;
        float q0 = 0, q1 = 0, q2 = 0, q3 = 0;
        if (gq < SEQ_T) {
            float4 v = *(const float4*)(qkv + bhBase + (size_t)gq * QKV_D + ld);
            int j0 = ld >> 1;
            float c0 = fc[(gq * 32 + j0) * 2 + 0], s0 = fc[(gq * 32 + j0) * 2 + 1];
            float c1 = fc[(gq * 32 + j0 + 1) * 2 + 0], s1 = fc[(gq * 32 + j0 + 1) * 2 + 1];
            q0 = v.x * c0 - v.y * s0;
            q1 = v.y * c0 + v.x * s0;
            q2 = v.z * c1 - v.w * s1;
            q3 = v.w * c1 + v.z * s1;
        }
        Qs[r * 65 + ld + 0] = q0;
        Qs[r * 65 + ld + 1] = q1;
        Qs[r * 65 + ld + 2] = q2;
        Qs[r * 65 + ld + 3] = q3;
    }

    float oacc[4][4] = {};
    float m[4], l[4];
#pragma unroll
    for (int i = 0; i < 4; i++) { m[i] = -1e30f; l[i] = 0.f; }

    const int nkt = qt + 1;
    for (int kt = 0; kt < nkt; kt++) {
#pragma unroll
        for (int i = 0; i < 4; i++) {
            int r = lr + 16 * i;
            int gk = kt * 64 + r;
            float k0 = 0, k1 = 0, k2 = 0, k3 = 0, v0 = 0, v1 = 0, v2 = 0, v3 = 0;
            if (gk < SEQ_T) {
                float4 kv = *(const float4*)(qkv + bhBase + (size_t)gk * QKV_D + 1024 + ld);
                float4 vv = *(const float4*)(qkv + bhBase + (size_t)gk * QKV_D + 2048 + ld);
                int j0 = ld >> 1;
                float c0 = fc[(gk * 32 + j0) * 2 + 0], s0 = fc[(gk * 32 + j0) * 2 + 1];
                float c1 = fc[(gk * 32 + j0 + 1) * 2 + 0], s1 = fc[(gk * 32 + j0 + 1) * 2 + 1];
                k0 = kv.x * c0 - kv.y * s0;
                k1 = kv.y * c0 + kv.x * s0;
                k2 = kv.z * c1 - kv.w * s1;
                k3 = kv.w * c1 + kv.z * s1;
                v0 = vv.x; v1 = vv.y; v2 = vv.z; v3 = vv.w;
            }
            Ks[r * 65 + ld + 0] = k0;
            Ks[r * 65 + ld + 1] = k1;
            Ks[r * 65 + ld + 2] = k2;
            Ks[r * 65 + ld + 3] = k3;
            Vs[r * 65 + ld + 0] = v0;
            Vs[r * 65 + ld + 1] = v1;
            Vs[r * 65 + ld + 2] = v2;
            Vs[r * 65 + ld + 3] = v3;
        }
        __syncthreads();

        float s[4][4] = {};
#pragma unroll 4
        for (int d = 0; d < 64; d++) {
            float ra[4], rb[4];
#pragma unroll
            for (int i = 0; i < 4; i++) ra[i] = Qs[(ty * 4 + i) * 65 + d];
#pragma unroll
            for (int j = 0; j < 4; j++) rb[j] = Ks[(tx * 4 + j) * 65 + d];
#pragma unroll
            for (int i = 0; i < 4; i++)
#pragma unroll
                for (int j = 0; j < 4; j++) s[i][j] += ra[i] * rb[j];
        }

#pragma unroll
        for (int i = 0; i < 4; i++) {
            int gq = qt * 64 + ty * 4 + i;
            float rm = -1e30f;
#pragma unroll
            for (int j = 0; j < 4; j++) {
                int gk = kt * 64 + tx * 4 + j;
                float sv = s[i][j] * 0.125f;
                if (gk > gq || gk >= SEQ_T) sv = -1e30f;
                s[i][j] = sv;
                rm = fmaxf(rm, sv);
            }
#pragma unroll
            for (int off = 8; off; off >>= 1)
                rm = fmaxf(rm, __shfl_xor_sync(0xffffffffu, rm, off));
            float newm = fmaxf(m[i], rm);
            float corr = __expf(m[i] - newm);
            float rs = 0.f;
#pragma unroll
            for (int j = 0; j < 4; j++) {
                float p = __expf(s[i][j] - newm);
                s[i][j] = p;
                rs += p;
            }
#pragma unroll
            for (int off = 8; off; off >>= 1)
                rs += __shfl_xor_sync(0xffffffffu, rs, off);
            l[i] = l[i] * corr + rs;
            m[i] = newm;
#pragma unroll
            for (int j = 0; j < 4; j++) oacc[i][j] *= corr;
        }

#pragma unroll
        for (int i = 0; i < 4; i++)
#pragma unroll
            for (int j = 0; j < 4; j++)
                Ps[(ty * 4 + i) * 65 + tx * 4 + j] = s[i][j];
        __syncthreads();

#pragma unroll 4
        for (int d = 0; d < 64; d++) {
            float ra[4], rb[4];
#pragma unroll
            for (int i = 0; i < 4; i++) ra[i] = Ps[(ty * 4 + i) * 65 + d];
#pragma unroll
            for (int j = 0; j < 4; j++) rb[j] = Vs[d * 65 + tx * 4 + j];
#pragma unroll
            for (int i = 0; i < 4; i++)
#pragma unroll
                for (int j = 0; j < 4; j++) oacc[i][j] += ra[i] * rb[j];
        }
        __syncthreads();
    }

#pragma unroll
    for (int i = 0; i < 4; i++) {
        int gq = qt * 64 + ty * 4 + i;
        if (gq >= SEQ_T) continue;
        float inv = 1.0f / l[i];
        float* op = o + ((size_t)bb * SEQ_T + gq) * EMBED_D + hh * HDIM + tx * 4;
        float4 r;
        r.x = oacc[i][0] * inv;
        r.y = oacc[i][1] * inv;
        r.z = oacc[i][2] * inv;
        r.w = oacc[i][3] * inv;
        *(float4*)op = r;
    }
}

// ---------------------------------------------------------------------------
// Launcher
// ---------------------------------------------------------------------------
extern "C" void kernel_launch(void* const* d_in, const int* in_sizes, int n_in,
                              void* d_out, int out_size) {
    const float* x       = (const float*)d_in[0];
    const float* cond    = (const float*)d_in[1];
    const float* patch_w = (const float*)d_in[2];
    const float* patch_b = (const float*)d_in[3];
    const float* ln_g    = (const float*)d_in[4];
    const float* ln_b    = (const float*)d_in[5];
    const float* pos     = (const float*)d_in[6];
    const float* cond_w  = (const float*)d_in[7];
    const float* cond_b  = (const float*)d_in[8];
    const float* wqkv    = (const float*)d_in[9];
    const float* wo      = (const float*)d_in[10];
    const float* w1      = (const float*)d_in[11];
    const float* w2      = (const float*)d_in[12];
    const float* w3      = (const float*)d_in[13];
    const float* anw     = (const float*)d_in[14];
    const float* fnw     = (const float*)d_in[15];

    float* h = (float*)d_out;

    float *a, *qkvb, *ob, *gate, *condb, *fc;
    cudaGetSymbolAddress((void**)&a, g_a);
    cudaGetSymbolAddress((void**)&qkvb, g_qkv);
    cudaGetSymbolAddress((void**)&ob, g_o);
    cudaGetSymbolAddress((void**)&gate, g_gate);
    cudaGetSymbolAddress((void**)&condb, g_cond);
    cudaGetSymbolAddress((void**)&fc, g_fc);

    cudaFuncSetAttribute(attn_kernel, cudaFuncAttributeMaxDynamicSharedMemorySize,
                         ATTN_SMEM);

    freqs_kernel<<<SEQ_T, 32>>>(fc);

    // patch embed -> g_a  (M=8192, K=768, N=1024)
    mma_gemm<1><<<dim3(EMBED_D / 128, PATCH_M / 128), 256>>>(
        x, patch_w, patch_b, a, PATCH_M, EMBED_D, PATCH_K);
    // cond embed -> g_cond (M=32)
    mma_gemm<1><<<dim3(EMBED_D / 128, 1), 256>>>(
        cond, cond_w, cond_b, condb, BATCH, EMBED_D, EMBED_D);

    embed_ln_kernel<<<ROWS_T, 256>>>(a, condb, pos, ln_g, ln_b, h);

    const int gy = (ROWS_T + 127) / 128;  // 65

    for (int blk = 0; blk < NBLK; blk++) {
        const float* Wqkv = wqkv + (size_t)blk * EMBED_D * QKV_D;
        const float* Wo   = wo   + (size_t)blk * EMBED_D * EMBED_D;
        const float* W1   = w1   + (size_t)blk * EMBED_D * HID_D;
        const float* W2   = w2   + (size_t)blk * HID_D * EMBED_D;
        const float* W3   = w3   + (size_t)blk * EMBED_D * HID_D;

        rmsnorm_kernel<<<ROWS_T, 256>>>(h, anw + blk * EMBED_D, a);
        mma_gemm<0><<<dim3(QKV_D / 128, gy), 256>>>(
            a, Wqkv, nullptr, qkvb, ROWS_T, QKV_D, EMBED_D);
        attn_kernel<<<dim3(5, NHEAD, BATCH), 256, ATTN_SMEM>>>(qkvb, fc, ob);
        mma_gemm<2><<<dim3(EMBED_D / 128, gy), 256>>>(
            ob, Wo, nullptr, h, ROWS_T, EMBED_D, EMBED_D);
        rmsnorm_kernel<<<ROWS_T, 256>>>(h, fnw + blk * EMBED_D, a);
        // gate = a @ W1
        mma_gemm<0><<<dim3(HID_D / 128, gy), 256>>>(
            a, W1, nullptr, gate, ROWS_T, HID_D, EMBED_D);
        // gate = silu(gate) * (a @ W3)
        mma_gemm<3><<<dim3(HID_D / 128, gy), 256>>>(
            a, W3, nullptr, gate, ROWS_T, HID_D, EMBED_D);
        // h += gate @ W2
        mma_gemm<2><<<dim3(EMBED_D / 128, gy), 256>>>(
            gate, W2, nullptr, h, ROWS_T, EMBED_D, HID_D);
    }
}